// round 1
// baseline (speedup 1.0000x reference)
#include <cuda_runtime.h>

#define DT 0.05f
#define N_STEPS 41

// Global accumulators: [0] = sum(err+eff), [1] = sum(nor). Doubles for accuracy.
__device__ double g_acc[2];

__global__ void zero_acc_kernel() {
    g_acc[0] = 0.0;
    g_acc[1] = 0.0;
}

__device__ __forceinline__ float tanh_fast(float x) {
    float y;
    asm("tanh.approx.f32 %0, %1;" : "=f"(y) : "f"(x));
    return y;
}

__global__ void __launch_bounds__(256) sim_kernel(
    const float* __restrict__ omega,
    const float* __restrict__ Wh1, const float* __restrict__ bh1,
    const float* __restrict__ Wh2, const float* __restrict__ bh2,
    const float* __restrict__ Wr1, const float* __restrict__ br1,
    const float* __restrict__ Wr2, const float* __restrict__ br2,
    int n)
{
    // Load shared tiny weights into registers (uniform, L1-hit after warm).
    float wh1[16], vbh1[4], wh2[4], vbh2;
    float wr1[9], vbr1[3], wr2[3], vbr2;
#pragma unroll
    for (int j = 0; j < 16; j++) wh1[j] = __ldg(Wh1 + j);
#pragma unroll
    for (int j = 0; j < 4; j++)  vbh1[j] = __ldg(bh1 + j);
#pragma unroll
    for (int j = 0; j < 4; j++)  wh2[j] = __ldg(Wh2 + j);
    vbh2 = __ldg(bh2);
#pragma unroll
    for (int j = 0; j < 9; j++)  wr1[j] = __ldg(Wr1 + j);
#pragma unroll
    for (int j = 0; j < 3; j++)  vbr1[j] = __ldg(br1 + j);
#pragma unroll
    for (int j = 0; j < 3; j++)  wr2[j] = __ldg(Wr2 + j);
    vbr2 = __ldg(br2);

    int i = blockIdx.x * blockDim.x + threadIdx.x;

    float v1 = 0.0f;  // err + eff for this task
    float v2 = 0.0f;  // nor for this task

    if (i < n) {
        const float star0 = omega[i];
        const float star1 = omega[n + i];

        float s0 = 0.0f, s1 = 0.0f;
        float err = 0.0f, eff = 0.0f, nor = 0.0f;

#pragma unroll 1
        for (int t = 0; t < N_STEPS - 1; t++) {
            float e0 = star0 - s0;
            float e1 = star1 - s1;
            err = fmaf(10.0f, e0 * e0, err);
            err = fmaf(e1, e1, err);
            float zt = fmaf(0.1f, e1, e0);

            // human MLP: xh = [star0, star1, s0, s1]
            float h0 = tanh_fast(fmaf(wh1[0], star0, fmaf(wh1[1], star1, fmaf(wh1[2], s0, fmaf(wh1[3], s1, vbh1[0])))));
            float h1 = tanh_fast(fmaf(wh1[4], star0, fmaf(wh1[5], star1, fmaf(wh1[6], s0, fmaf(wh1[7], s1, vbh1[1])))));
            float h2 = tanh_fast(fmaf(wh1[8], star0, fmaf(wh1[9], star1, fmaf(wh1[10], s0, fmaf(wh1[11], s1, vbh1[2])))));
            float h3 = tanh_fast(fmaf(wh1[12], star0, fmaf(wh1[13], star1, fmaf(wh1[14], s0, fmaf(wh1[15], s1, vbh1[3])))));
            float z  = tanh_fast(fmaf(wh2[0], h0, fmaf(wh2[1], h1, fmaf(wh2[2], h2, fmaf(wh2[3], h3, vbh2)))));

            // robot MLP: xr = [s0, s1, z]
            float r0 = tanh_fast(fmaf(wr1[0], s0, fmaf(wr1[1], s1, fmaf(wr1[2], z, vbr1[0]))));
            float r1 = tanh_fast(fmaf(wr1[3], s0, fmaf(wr1[4], s1, fmaf(wr1[5], z, vbr1[1]))));
            float r2 = tanh_fast(fmaf(wr1[6], s0, fmaf(wr1[7], s1, fmaf(wr1[8], z, vbr1[2]))));
            float a  = fmaf(wr2[0], r0, fmaf(wr2[1], r1, fmaf(wr2[2], r2, vbr2)));

            // s_next = [s0 + dt*s1, s1 + dt*a]
            float ns0 = fmaf(DT, s1, s0);
            float ns1 = fmaf(DT, a, s1);
            s0 = ns0;
            s1 = ns1;

            eff += (fabsf(z) > 0.01f) ? 1.0f : 0.0f;
            float d = zt - z;
            nor = fmaf(d, d, nor);
        }

        // final error term
        float e0 = star0 - s0;
        float e1 = star1 - s1;
        err = fmaf(10.0f, e0 * e0, err);
        err = fmaf(e1, e1, err);

        v1 = err + eff;
        v2 = nor;
    }

    // warp reduce
#pragma unroll
    for (int off = 16; off > 0; off >>= 1) {
        v1 += __shfl_down_sync(0xFFFFFFFFu, v1, off);
        v2 += __shfl_down_sync(0xFFFFFFFFu, v2, off);
    }

    __shared__ float s1buf[8];
    __shared__ float s2buf[8];
    int lane = threadIdx.x & 31;
    int wid  = threadIdx.x >> 5;
    if (lane == 0) { s1buf[wid] = v1; s2buf[wid] = v2; }
    __syncthreads();

    if (wid == 0) {
        float a1 = (lane < 8) ? s1buf[lane] : 0.0f;
        float a2 = (lane < 8) ? s2buf[lane] : 0.0f;
#pragma unroll
        for (int off = 4; off > 0; off >>= 1) {
            a1 += __shfl_down_sync(0xFFFFFFFFu, a1, off);
            a2 += __shfl_down_sync(0xFFFFFFFFu, a2, off);
        }
        if (lane == 0) {
            atomicAdd(&g_acc[0], (double)a1);
            atomicAdd(&g_acc[1], (double)a2);
        }
    }
}

__global__ void finalize_kernel(const float* __restrict__ alpha, float* __restrict__ out, int n) {
    double inv_n = 1.0 / (double)n;
    out[0] = (float)((g_acc[0] + (double)alpha[0] * g_acc[1]) * inv_n);
}

extern "C" void kernel_launch(void* const* d_in, const int* in_sizes, int n_in,
                              void* d_out, int out_size) {
    const float* omega = (const float*)d_in[0];
    const float* Wh1   = (const float*)d_in[1];
    const float* bh1   = (const float*)d_in[2];
    const float* Wh2   = (const float*)d_in[3];
    const float* bh2   = (const float*)d_in[4];
    const float* Wr1   = (const float*)d_in[5];
    const float* br1   = (const float*)d_in[6];
    const float* Wr2   = (const float*)d_in[7];
    const float* br2   = (const float*)d_in[8];
    const float* alpha = (const float*)d_in[9];
    float* out = (float*)d_out;

    int n = in_sizes[0] / 2;  // omega is [2, N]

    zero_acc_kernel<<<1, 1>>>();
    int threads = 256;
    int blocks = (n + threads - 1) / threads;
    sim_kernel<<<blocks, threads>>>(omega, Wh1, bh1, Wh2, bh2, Wr1, br1, Wr2, br2, n);
    finalize_kernel<<<1, 1>>>(alpha, out, n);
}

// round 2
// speedup vs baseline: 1.0714x; 1.0714x over previous
#include <cuda_runtime.h>
#include <cuda_fp16.h>

#define DT 0.05f
#define N_STEPS 41

typedef unsigned long long u64;

// Global accumulators: [0] = sum(err+eff), [1] = sum(nor). Doubles for accuracy.
__device__ double g_acc[2];

__global__ void zero_acc_kernel() {
    g_acc[0] = 0.0;
    g_acc[1] = 0.0;
}

// ---- f32x2 packed helpers (SASS FFMA2/FMUL2 — only reachable via PTX) ----
__device__ __forceinline__ u64 pack2(float lo, float hi) {
    u64 r; asm("mov.b64 %0, {%1, %2};" : "=l"(r) : "f"(lo), "f"(hi)); return r;
}
__device__ __forceinline__ void unpack2(u64 v, float& lo, float& hi) {
    asm("mov.b64 {%0, %1}, %2;" : "=f"(lo), "=f"(hi) : "l"(v));
}
__device__ __forceinline__ u64 fma2(u64 a, u64 b, u64 c) {
    u64 d; asm("fma.rn.f32x2 %0, %1, %2, %3;" : "=l"(d) : "l"(a), "l"(b), "l"(c)); return d;
}
__device__ __forceinline__ u64 mul2(u64 a, u64 b) {
    u64 d; asm("mul.rn.f32x2 %0, %1, %2;" : "=l"(d) : "l"(a), "l"(b)); return d;
}

// tanh of both lanes via one MUFU f16x2 op.
__device__ __forceinline__ u64 tanh2(u64 v) {
    float lo, hi; unpack2(v, lo, hi);
    __half2 h = __floats2half2_rn(lo, hi);
    unsigned int hb = *reinterpret_cast<unsigned int*>(&h);
    asm("tanh.approx.f16x2 %0, %0;" : "+r"(hb));
    h = *reinterpret_cast<__half2*>(&hb);
    float2 f = __half22float2(h);
    return pack2(f.x, f.y);
}

__global__ void __launch_bounds__(128) sim_kernel(
    const float* __restrict__ omega,
    const float* __restrict__ Wh1, const float* __restrict__ bh1,
    const float* __restrict__ Wh2, const float* __restrict__ bh2,
    const float* __restrict__ Wr1, const float* __restrict__ br1,
    const float* __restrict__ Wr2, const float* __restrict__ br2,
    int n)
{
    const int half = n >> 1;           // n is even (1048576)
    const int i = blockIdx.x * blockDim.x + threadIdx.x;

    float v1 = 0.0f, v2 = 0.0f;

    if (i < half) {
        // Two tasks per thread: lane-lo = task i, lane-hi = task i+half.
        const float st0_lo = omega[i],         st0_hi = omega[i + half];
        const float st1_lo = omega[n + i],     st1_hi = omega[n + i + half];
        const u64 star0 = pack2(st0_lo, st0_hi);
        const u64 star1 = pack2(st1_lo, st1_hi);

        // Broadcast scalar weights into packed registers (loop-invariant).
        // Human layer1: per neuron j, c_h[j] = W[j,0]*star0 + W[j,1]*star1 + b[j] (invariant);
        // inside loop only W[j,2]*s0 + W[j,3]*s1 remains.
        u64 whA[4], whB[4], c_h[4];
#pragma unroll
        for (int j = 0; j < 4; j++) {
            float w0 = __ldg(Wh1 + 4*j + 0), w1 = __ldg(Wh1 + 4*j + 1);
            float w2 = __ldg(Wh1 + 4*j + 2), w3 = __ldg(Wh1 + 4*j + 3);
            float b  = __ldg(bh1 + j);
            float clo = fmaf(w0, st0_lo, fmaf(w1, st1_lo, b));
            float chi = fmaf(w0, st0_hi, fmaf(w1, st1_hi, b));
            c_h[j] = pack2(clo, chi);
            whA[j] = pack2(w2, w2);
            whB[j] = pack2(w3, w3);
        }
        u64 wh2v[4], bh2v;
#pragma unroll
        for (int j = 0; j < 4; j++) { float w = __ldg(Wh2 + j); wh2v[j] = pack2(w, w); }
        { float b = __ldg(bh2); bh2v = pack2(b, b); }

        u64 wrS0[3], wrS1[3], wrZ[3], br1v[3];
#pragma unroll
        for (int j = 0; j < 3; j++) {
            float w0 = __ldg(Wr1 + 3*j + 0), w1 = __ldg(Wr1 + 3*j + 1), w2 = __ldg(Wr1 + 3*j + 2);
            float b  = __ldg(br1 + j);
            wrS0[j] = pack2(w0, w0); wrS1[j] = pack2(w1, w1); wrZ[j] = pack2(w2, w2);
            br1v[j] = pack2(b, b);
        }
        u64 wr2v[3], br2v;
#pragma unroll
        for (int j = 0; j < 3; j++) { float w = __ldg(Wr2 + j); wr2v[j] = pack2(w, w); }
        { float b = __ldg(br2); br2v = pack2(b, b); }

        const u64 neg1 = pack2(-1.0f, -1.0f);
        const u64 ten  = pack2(10.0f, 10.0f);
        const u64 c01  = pack2(0.1f, 0.1f);
        const u64 dt2  = pack2(DT, DT);

        u64 s0 = 0ull, s1 = 0ull;       // packed (0.0f, 0.0f)
        u64 err = 0ull, nor = 0ull;
        float eff_lo = 0.0f, eff_hi = 0.0f;

#pragma unroll 1
        for (int t = 0; t < N_STEPS - 1; t++) {
            u64 e0 = fma2(neg1, s0, star0);
            u64 e1 = fma2(neg1, s1, star1);
            err = fma2(ten, mul2(e0, e0), err);
            err = fma2(e1, e1, err);
            u64 zt = fma2(c01, e1, e0);

            // human MLP (star part precomputed in c_h)
            u64 h0 = tanh2(fma2(whB[0], s1, fma2(whA[0], s0, c_h[0])));
            u64 h1 = tanh2(fma2(whB[1], s1, fma2(whA[1], s0, c_h[1])));
            u64 h2 = tanh2(fma2(whB[2], s1, fma2(whA[2], s0, c_h[2])));
            u64 h3 = tanh2(fma2(whB[3], s1, fma2(whA[3], s0, c_h[3])));
            u64 pz = fma2(wh2v[3], h3, fma2(wh2v[2], h2, fma2(wh2v[1], h1, fma2(wh2v[0], h0, bh2v))));
            u64 z  = tanh2(pz);

            // robot MLP
            u64 r0 = tanh2(fma2(wrS1[0], s1, fma2(wrS0[0], s0, fma2(wrZ[0], z, br1v[0]))));
            u64 r1 = tanh2(fma2(wrS1[1], s1, fma2(wrS0[1], s0, fma2(wrZ[1], z, br1v[1]))));
            u64 r2 = tanh2(fma2(wrS1[2], s1, fma2(wrS0[2], s0, fma2(wrZ[2], z, br1v[2]))));
            u64 a  = fma2(wr2v[2], r2, fma2(wr2v[1], r1, fma2(wr2v[0], r0, br2v)));

            // state update
            s0 = fma2(dt2, s1, s0);
            s1 = fma2(dt2, a, s1);

            // eff (per-lane scalar)
            float z_lo, z_hi; unpack2(z, z_lo, z_hi);
            eff_lo += (fabsf(z_lo) > 0.01f) ? 1.0f : 0.0f;
            eff_hi += (fabsf(z_hi) > 0.01f) ? 1.0f : 0.0f;

            // nor
            u64 d = fma2(neg1, z, zt);
            nor = fma2(d, d, nor);
        }

        // final error term
        u64 e0 = fma2(neg1, s0, star0);
        u64 e1 = fma2(neg1, s1, star1);
        err = fma2(ten, mul2(e0, e0), err);
        err = fma2(e1, e1, err);

        float err_lo, err_hi, nor_lo, nor_hi;
        unpack2(err, err_lo, err_hi);
        unpack2(nor, nor_lo, nor_hi);
        v1 = (err_lo + eff_lo) + (err_hi + eff_hi);
        v2 = nor_lo + nor_hi;
    }

    // warp reduce
#pragma unroll
    for (int off = 16; off > 0; off >>= 1) {
        v1 += __shfl_down_sync(0xFFFFFFFFu, v1, off);
        v2 += __shfl_down_sync(0xFFFFFFFFu, v2, off);
    }

    __shared__ float s1buf[4];
    __shared__ float s2buf[4];
    int lane = threadIdx.x & 31;
    int wid  = threadIdx.x >> 5;
    if (lane == 0) { s1buf[wid] = v1; s2buf[wid] = v2; }
    __syncthreads();

    if (wid == 0) {
        float a1 = (lane < 4) ? s1buf[lane] : 0.0f;
        float a2 = (lane < 4) ? s2buf[lane] : 0.0f;
#pragma unroll
        for (int off = 2; off > 0; off >>= 1) {
            a1 += __shfl_down_sync(0xFFFFFFFFu, a1, off);
            a2 += __shfl_down_sync(0xFFFFFFFFu, a2, off);
        }
        if (lane == 0) {
            atomicAdd(&g_acc[0], (double)a1);
            atomicAdd(&g_acc[1], (double)a2);
        }
    }
}

__global__ void finalize_kernel(const float* __restrict__ alpha, float* __restrict__ out, int n) {
    double inv_n = 1.0 / (double)n;
    out[0] = (float)((g_acc[0] + (double)alpha[0] * g_acc[1]) * inv_n);
}

extern "C" void kernel_launch(void* const* d_in, const int* in_sizes, int n_in,
                              void* d_out, int out_size) {
    const float* omega = (const float*)d_in[0];
    const float* Wh1   = (const float*)d_in[1];
    const float* bh1   = (const float*)d_in[2];
    const float* Wh2   = (const float*)d_in[3];
    const float* bh2   = (const float*)d_in[4];
    const float* Wr1   = (const float*)d_in[5];
    const float* br1   = (const float*)d_in[6];
    const float* Wr2   = (const float*)d_in[7];
    const float* br2   = (const float*)d_in[8];
    const float* alpha = (const float*)d_in[9];
    float* out = (float*)d_out;

    int n = in_sizes[0] / 2;  // omega is [2, N]
    int half = n >> 1;

    zero_acc_kernel<<<1, 1>>>();
    int threads = 128;
    int blocks = (half + threads - 1) / threads;
    sim_kernel<<<blocks, threads>>>(omega, Wh1, bh1, Wh2, bh2, Wr1, br1, Wr2, br2, n);
    finalize_kernel<<<1, 1>>>(alpha, out, n);
}

// round 3
// speedup vs baseline: 1.1981x; 1.1183x over previous
#include <cuda_runtime.h>
#include <cuda_fp16.h>

#define DT 0.05f
#define N_STEPS 41

typedef unsigned long long u64;

// Global accumulators: [0] = sum(err+eff), [1] = sum(nor). Zero-initialized at
// module load; the LAST block of each launch resets them after reading, so the
// kernel is replay-deterministic under graph capture.
__device__ double g_acc[2] = {0.0, 0.0};
__device__ unsigned int g_count = 0;

// ---- f32x2 packed helpers (SASS FFMA2 — only reachable via PTX) ----
__device__ __forceinline__ u64 pack2(float lo, float hi) {
    u64 r; asm("mov.b64 %0, {%1, %2};" : "=l"(r) : "f"(lo), "f"(hi)); return r;
}
__device__ __forceinline__ void unpack2(u64 v, float& lo, float& hi) {
    asm("mov.b64 {%0, %1}, %2;" : "=f"(lo), "=f"(hi) : "l"(v));
}
__device__ __forceinline__ u64 fma2(u64 a, u64 b, u64 c) {
    u64 d; asm("fma.rn.f32x2 %0, %1, %2, %3;" : "=l"(d) : "l"(a), "l"(b), "l"(c)); return d;
}
__device__ __forceinline__ u64 mul2(u64 a, u64 b) {
    u64 d; asm("mul.rn.f32x2 %0, %1, %2;" : "=l"(d) : "l"(a), "l"(b)); return d;
}

// tanh on a half2 (both lanes), one MUFU op, no conversions.
__device__ __forceinline__ __half2 tanh_h2(__half2 x) {
    unsigned int b = *reinterpret_cast<unsigned int*>(&x);
    asm("tanh.approx.f16x2 %0, %0;" : "+r"(b));
    return *reinterpret_cast<__half2*>(&b);
}

__global__ void __launch_bounds__(128) sim_kernel(
    const float* __restrict__ omega,
    const float* __restrict__ Wh1, const float* __restrict__ bh1,
    const float* __restrict__ Wh2, const float* __restrict__ bh2,
    const float* __restrict__ Wr1, const float* __restrict__ br1,
    const float* __restrict__ Wr2, const float* __restrict__ br2,
    const float* __restrict__ alpha,
    float* __restrict__ out,
    int n)
{
    const int half = n >> 1;           // n is even (1048576)
    const int i = blockIdx.x * blockDim.x + threadIdx.x;

    float v1 = 0.0f, v2 = 0.0f;

    if (i < half) {
        // Two tasks per thread: half2/f32x2 lane-lo = task i, lane-hi = task i+half.
        const float st0_lo = omega[i],     st0_hi = omega[i + half];
        const float st1_lo = omega[n + i], st1_hi = omega[n + i + half];
        const u64 star0 = pack2(st0_lo, st0_hi);
        const u64 star1 = pack2(st1_lo, st1_hi);

        // ---- pre-packed half2 weights (broadcast both lanes) ----
        // Human layer1: star-dependent part folded into per-task bias c_h.
        __half2 whA[4], whB[4], c_h[4];
#pragma unroll
        for (int j = 0; j < 4; j++) {
            float w0 = __ldg(Wh1 + 4*j + 0), w1 = __ldg(Wh1 + 4*j + 1);
            float w2 = __ldg(Wh1 + 4*j + 2), w3 = __ldg(Wh1 + 4*j + 3);
            float b  = __ldg(bh1 + j);
            float clo = fmaf(w0, st0_lo, fmaf(w1, st1_lo, b));
            float chi = fmaf(w0, st0_hi, fmaf(w1, st1_hi, b));
            c_h[j] = __floats2half2_rn(clo, chi);
            whA[j] = __float2half2_rn(w2);
            whB[j] = __float2half2_rn(w3);
        }
        __half2 wh2v[4], bh2v;
#pragma unroll
        for (int j = 0; j < 4; j++) wh2v[j] = __float2half2_rn(__ldg(Wh2 + j));
        bh2v = __float2half2_rn(__ldg(bh2));

        __half2 wrS0[3], wrS1[3], wrZ[3], br1v[3];
#pragma unroll
        for (int j = 0; j < 3; j++) {
            wrS0[j] = __float2half2_rn(__ldg(Wr1 + 3*j + 0));
            wrS1[j] = __float2half2_rn(__ldg(Wr1 + 3*j + 1));
            wrZ[j]  = __float2half2_rn(__ldg(Wr1 + 3*j + 2));
            br1v[j] = __float2half2_rn(__ldg(br1 + j));
        }
        __half2 wr2v[3], br2v;
#pragma unroll
        for (int j = 0; j < 3; j++) wr2v[j] = __float2half2_rn(__ldg(Wr2 + j));
        br2v = __float2half2_rn(__ldg(br2));

        const u64 neg1 = pack2(-1.0f, -1.0f);
        const u64 ten  = pack2(10.0f, 10.0f);
        const u64 c01  = pack2(0.1f, 0.1f);
        const u64 dt2  = pack2(DT, DT);
        const __half2 thr = __float2half2_rn(0.01f);

        u64 s0 = 0ull, s1 = 0ull;       // packed (0.0f, 0.0f)
        u64 err = 0ull, nor = 0ull;
        __half2 eff = __float2half2_rn(0.0f);  // integer counts <= 40, exact in f16

#pragma unroll 1
        for (int t = 0; t < N_STEPS - 1; t++) {
            // f32x2 outer dynamics
            u64 e0 = fma2(neg1, s0, star0);
            u64 e1 = fma2(neg1, s1, star1);
            err = fma2(ten, mul2(e0, e0), err);
            err = fma2(e1, e1, err);
            u64 zt = fma2(c01, e1, e0);

            // state -> half2 (one cvt each)
            float s0lo, s0hi, s1lo, s1hi;
            unpack2(s0, s0lo, s0hi);
            unpack2(s1, s1lo, s1hi);
            __half2 s0h = __floats2half2_rn(s0lo, s0hi);
            __half2 s1h = __floats2half2_rn(s1lo, s1hi);

            // human MLP, all half2 (star part folded into c_h)
            __half2 h0 = tanh_h2(__hfma2(whB[0], s1h, __hfma2(whA[0], s0h, c_h[0])));
            __half2 h1 = tanh_h2(__hfma2(whB[1], s1h, __hfma2(whA[1], s0h, c_h[1])));
            __half2 h2 = tanh_h2(__hfma2(whB[2], s1h, __hfma2(whA[2], s0h, c_h[2])));
            __half2 h3 = tanh_h2(__hfma2(whB[3], s1h, __hfma2(whA[3], s0h, c_h[3])));
            __half2 z  = tanh_h2(__hfma2(wh2v[3], h3, __hfma2(wh2v[2], h2,
                                 __hfma2(wh2v[1], h1, __hfma2(wh2v[0], h0, bh2v)))));

            // robot MLP, all half2
            __half2 r0 = tanh_h2(__hfma2(wrZ[0], z, __hfma2(wrS1[0], s1h, __hfma2(wrS0[0], s0h, br1v[0]))));
            __half2 r1 = tanh_h2(__hfma2(wrZ[1], z, __hfma2(wrS1[1], s1h, __hfma2(wrS0[1], s0h, br1v[1]))));
            __half2 r2 = tanh_h2(__hfma2(wrZ[2], z, __hfma2(wrS1[2], s1h, __hfma2(wrS0[2], s0h, br1v[2]))));
            __half2 ah = __hfma2(wr2v[2], r2, __hfma2(wr2v[1], r1, __hfma2(wr2v[0], r0, br2v)));

            // a -> f32x2, state update in f32x2
            float2 af = __half22float2(ah);
            s0 = fma2(dt2, s1, s0);
            s1 = fma2(dt2, pack2(af.x, af.y), s1);

            // eff: half2 compare produces 1.0/0.0 per lane
            eff = __hadd2(eff, __hgt2(__habs2(z), thr));

            // nor in f32x2 (z converted once)
            float2 zf = __half22float2(z);
            u64 d = fma2(neg1, pack2(zf.x, zf.y), zt);
            nor = fma2(d, d, nor);
        }

        // final error term
        u64 e0 = fma2(neg1, s0, star0);
        u64 e1 = fma2(neg1, s1, star1);
        err = fma2(ten, mul2(e0, e0), err);
        err = fma2(e1, e1, err);

        float err_lo, err_hi, nor_lo, nor_hi;
        unpack2(err, err_lo, err_hi);
        unpack2(nor, nor_lo, nor_hi);
        float2 efff = __half22float2(eff);
        v1 = (err_lo + efff.x) + (err_hi + efff.y);
        v2 = nor_lo + nor_hi;
    }

    // warp reduce
#pragma unroll
    for (int off = 16; off > 0; off >>= 1) {
        v1 += __shfl_down_sync(0xFFFFFFFFu, v1, off);
        v2 += __shfl_down_sync(0xFFFFFFFFu, v2, off);
    }

    __shared__ float s1buf[4];
    __shared__ float s2buf[4];
    int lane = threadIdx.x & 31;
    int wid  = threadIdx.x >> 5;
    if (lane == 0) { s1buf[wid] = v1; s2buf[wid] = v2; }
    __syncthreads();

    __shared__ bool is_last;
    if (threadIdx.x == 0) {
        float a1 = s1buf[0] + s1buf[1] + s1buf[2] + s1buf[3];
        float a2 = s2buf[0] + s2buf[1] + s2buf[2] + s2buf[3];
        atomicAdd(&g_acc[0], (double)a1);
        atomicAdd(&g_acc[1], (double)a2);
        __threadfence();
        unsigned int ticket = atomicAdd(&g_count, 1u);
        is_last = (ticket == gridDim.x - 1);
    }
    __syncthreads();

    // Tail block: finalize and reset accumulators for the next graph replay.
    if (is_last && threadIdx.x == 0) {
        double tot = (g_acc[0] + (double)alpha[0] * g_acc[1]) / (double)n;
        out[0] = (float)tot;
        g_acc[0] = 0.0;
        g_acc[1] = 0.0;
        g_count  = 0u;
        __threadfence();
    }
}

extern "C" void kernel_launch(void* const* d_in, const int* in_sizes, int n_in,
                              void* d_out, int out_size) {
    const float* omega = (const float*)d_in[0];
    const float* Wh1   = (const float*)d_in[1];
    const float* bh1   = (const float*)d_in[2];
    const float* Wh2   = (const float*)d_in[3];
    const float* bh2   = (const float*)d_in[4];
    const float* Wr1   = (const float*)d_in[5];
    const float* br1   = (const float*)d_in[6];
    const float* Wr2   = (const float*)d_in[7];
    const float* br2   = (const float*)d_in[8];
    const float* alpha = (const float*)d_in[9];
    float* out = (float*)d_out;

    int n = in_sizes[0] / 2;  // omega is [2, N]
    int half = n >> 1;

    int threads = 128;
    int blocks = (half + threads - 1) / threads;
    sim_kernel<<<blocks, threads>>>(omega, Wh1, bh1, Wh2, bh2, Wr1, br1, Wr2, br2,
                                    alpha, out, n);
}